// round 14
// baseline (speedup 1.0000x reference)
#include <cuda_runtime.h>
#include <cuda_fp16.h>
#include <math.h>

#define NN 50000
#define EE 800000
#define HCD 128
#define HEADS 4
#define OUTC 64
#define ED 32
#define NEG 0.2f

// ---------------- scratch (device globals) ------------------------------------
__device__ __half g_xl1h[NN * HCD];   // fp16 source-transform
__device__ float  g_xr1[NN * HCD];
__device__ float  g_h  [NN * HCD];
__device__ __half g_xl2h[NN * OUTC];
__device__ float  g_xr2[NN * OUTC];
__device__ int    g_deg[NN];
__device__ int    g_rowptr[NN + 1];
__device__ int    g_cursor[NN];
__device__ int4   g_sde[EE];          // CSR slot -> {src, dst, edge, 0}
// pre-packed tf32 B-fragments: [kt][ntg][lane]{b0,b1}
__device__ uint2 g_W1p[16 * 32 * 32];
__device__ uint2 g_W2p[16 * 16 * 32];
__device__ uint2 g_We1p[4 * 16 * 32];
__device__ uint2 g_We2p[4 * 8 * 32];

// ---------------- helpers -------------------------------------------------------
__device__ __forceinline__ unsigned tf32_of(float f) {
    unsigned r;
    asm("cvt.rna.tf32.f32 %0, %1;" : "=r"(r) : "f"(f));
    return r;
}
__device__ __forceinline__ void mma_tf32(float* d,
                                         unsigned a0, unsigned a1, unsigned a2, unsigned a3,
                                         unsigned b0, unsigned b1) {
    asm volatile(
        "mma.sync.aligned.m16n8k8.row.col.f32.tf32.tf32.f32 "
        "{%0,%1,%2,%3}, {%4,%5,%6,%7}, {%8,%9}, {%0,%1,%2,%3};"
        : "+f"(d[0]), "+f"(d[1]), "+f"(d[2]), "+f"(d[3])
        : "r"(a0), "r"(a1), "r"(a2), "r"(a3), "r"(b0), "r"(b1));
}
__device__ __forceinline__ float lrelu(float x) { return x > 0.f ? x : NEG * x; }

// ---------------- weight fragment pre-pack --------------------------------------
__global__ void prepack_kernel(const float* __restrict__ Wl1, const float* __restrict__ Wr1,
                               const float* __restrict__ Wl2, const float* __restrict__ Wr2,
                               const float* __restrict__ We1, const float* __restrict__ We2) {
    int gw = blockIdx.x * 8 + (threadIdx.x >> 5);
    int lane = threadIdx.x & 31, g = lane >> 2, t4 = lane & 3;
    if (gw < 512) {
        int kt = gw >> 5, ntg = gw & 31;
        int c = ntg * 8 + g, k0 = kt * 8 + t4;
        float v0 = (c < 128) ? Wl1[k0 * 128 + c] : Wr1[k0 * 128 + c - 128];
        float v1 = (c < 128) ? Wl1[(k0 + 4) * 128 + c] : Wr1[(k0 + 4) * 128 + c - 128];
        g_W1p[(kt * 32 + ntg) * 32 + lane] = make_uint2(tf32_of(v0), tf32_of(v1));
    } else if (gw < 768) {
        int r = gw - 512;
        int kt = r >> 4, ntg = r & 15;
        int c = ntg * 8 + g, k0 = kt * 8 + t4;
        float v0 = (c < 64) ? Wl2[k0 * 64 + c] : Wr2[k0 * 64 + c - 64];
        float v1 = (c < 64) ? Wl2[(k0 + 4) * 64 + c] : Wr2[(k0 + 4) * 64 + c - 64];
        g_W2p[(kt * 16 + ntg) * 32 + lane] = make_uint2(tf32_of(v0), tf32_of(v1));
    } else if (gw < 832) {
        int r = gw - 768;
        int kt = r >> 4, ntg = r & 15;
        int c = ntg * 8 + g, k0 = kt * 8 + t4;
        g_We1p[(kt * 16 + ntg) * 32 + lane] =
            make_uint2(tf32_of(We1[k0 * 128 + c]), tf32_of(We1[(k0 + 4) * 128 + c]));
    } else if (gw < 864) {
        int r = gw - 832;
        int kt = r >> 3, ntg = r & 7;
        int c = ntg * 8 + g, k0 = kt * 8 + t4;
        g_We2p[(kt * 8 + ntg) * 32 + lane] =
            make_uint2(tf32_of(We2[k0 * 64 + c]), tf32_of(We2[(k0 + 4) * 64 + c]));
    }
}

// ---------------- CSR build -----------------------------------------------------
__global__ void csr_count_kernel(const int* __restrict__ dst) {
    int t = blockIdx.x * blockDim.x + threadIdx.x;
    int e4 = t * 4;
    if (e4 < EE) {
        int4 d = *(const int4*)&dst[e4];
        atomicAdd(&g_deg[d.x], 1);
        atomicAdd(&g_deg[d.y], 1);
        atomicAdd(&g_deg[d.z], 1);
        atomicAdd(&g_deg[d.w], 1);
    }
}

__global__ void scan_kernel() {
    __shared__ int wtot[32];
    __shared__ int carry_sm;
    int t = threadIdx.x, lane = t & 31, wid = t >> 5;
    if (t == 0) carry_sm = 0;
    __syncthreads();
    for (int base = 0; base < NN; base += 4096) {
        int carry = carry_sm;
        int idx = base + t * 4;
        int4 v = make_int4(0, 0, 0, 0);
        if (idx + 3 < NN) v = *(const int4*)&g_deg[idx];
        else {
            if (idx     < NN) v.x = g_deg[idx];
            if (idx + 1 < NN) v.y = g_deg[idx + 1];
            if (idx + 2 < NN) v.z = g_deg[idx + 2];
        }
        int s1 = v.x + v.y, s2 = s1 + v.z, tsum = s2 + v.w;
        int sc = tsum;
        #pragma unroll
        for (int off = 1; off < 32; off <<= 1) {
            int u = __shfl_up_sync(0xffffffffu, sc, off);
            if (lane >= off) sc += u;
        }
        if (lane == 31) wtot[wid] = sc;
        __syncthreads();
        if (wid == 0) {
            int wv = wtot[lane];
            int ws = wv;
            #pragma unroll
            for (int off = 1; off < 32; off <<= 1) {
                int u = __shfl_up_sync(0xffffffffu, ws, off);
                if (lane >= off) ws += u;
            }
            wtot[lane] = ws - wv;
        }
        __syncthreads();
        int off0 = carry + wtot[wid] + (sc - tsum);
        if (idx     < NN) { g_rowptr[idx]     = off0;        g_cursor[idx]     = off0; }
        if (idx + 1 < NN) { int o = off0 + v.x; g_rowptr[idx + 1] = o; g_cursor[idx + 1] = o; }
        if (idx + 2 < NN) { int o = off0 + s1;  g_rowptr[idx + 2] = o; g_cursor[idx + 2] = o; }
        if (idx + 3 < NN) { int o = off0 + s2;  g_rowptr[idx + 3] = o; g_cursor[idx + 3] = o; }
        if (t == 1023) carry_sm = carry + wtot[31] + sc;
        __syncthreads();
    }
    if (t == 0) g_rowptr[NN] = EE;
}

__global__ void csr_fill_kernel(const int* __restrict__ src, const int* __restrict__ dst) {
    int e = blockIdx.x * blockDim.x + threadIdx.x;
    if (e < EE) {
        int d = dst[e];
        int pos = atomicAdd(&g_cursor[d], 1);
        g_sde[pos] = make_int4(src[e], d, e, 0);
    }
}

// ---------------- node transform: smem-staged A + direct-LDG B tf32 MMA ---------
template<int OUTD, int TC>
__global__ __launch_bounds__(256) void transform_staged(
    const float* __restrict__ x, const uint2* __restrict__ Wp,
    const float* __restrict__ bl, const float* __restrict__ br,
    __half* __restrict__ xlh, float* __restrict__ xr) {
    constexpr int NTT = TC / 8;
    __shared__ unsigned xs[128 * 68];
    int tid = threadIdx.x;
    int w = tid >> 5, lane = tid & 31, g = lane >> 2, t4 = lane & 3;
    int mrow = w & 3, ncol = w >> 2;
    int node0 = blockIdx.x * 128;
    int rbase = mrow * 32;
    int ntbase = blockIdx.y * 16 + ncol * 8;

    float acc[2][8][4];
    #pragma unroll
    for (int mt = 0; mt < 2; mt++)
        #pragma unroll
        for (int nt = 0; nt < 8; nt++)
            #pragma unroll
            for (int i = 0; i < 4; i++) acc[mt][nt][i] = 0.f;

    #pragma unroll
    for (int ch = 0; ch < 2; ch++) {
        __syncthreads();
        for (int idx = tid; idx < 128 * 16; idx += 256) {
            int r = idx >> 4, q = idx & 15;
            int row = node0 + r;
            float4 v = make_float4(0.f, 0.f, 0.f, 0.f);
            if (row < NN) v = *(const float4*)&x[row * 128 + ch * 64 + q * 4];
            uint4 u;
            u.x = tf32_of(v.x); u.y = tf32_of(v.y);
            u.z = tf32_of(v.z); u.w = tf32_of(v.w);
            *(uint4*)&xs[r * 68 + q * 4] = u;
        }
        __syncthreads();
        #pragma unroll
        for (int ktl = 0; ktl < 8; ktl++) {
            int kt = ch * 8 + ktl;
            unsigned a[2][4];
            #pragma unroll
            for (int mt = 0; mt < 2; mt++) {
                int r0 = (rbase + mt * 16 + g) * 68 + ktl * 8 + t4;
                a[mt][0] = xs[r0];
                a[mt][1] = xs[r0 + 8 * 68];
                a[mt][2] = xs[r0 + 4];
                a[mt][3] = xs[r0 + 8 * 68 + 4];
            }
            const uint2* wrow = Wp + (kt * NTT + ntbase) * 32 + lane;
            #pragma unroll
            for (int nt = 0; nt < 8; nt++) {
                uint2 b = __ldg(wrow + nt * 32);
                mma_tf32(acc[0][nt], a[0][0], a[0][1], a[0][2], a[0][3], b.x, b.y);
                mma_tf32(acc[1][nt], a[1][0], a[1][1], a[1][2], a[1][3], b.x, b.y);
            }
        }
    }

    #pragma unroll
    for (int nt = 0; nt < 8; nt++) {
        int c = (ntbase + nt) * 8 + t4 * 2;
        if (c < OUTD) {
            float2 bv = *(const float2*)&bl[c];
            #pragma unroll
            for (int mt = 0; mt < 2; mt++) {
                int n0v = node0 + rbase + mt * 16 + g;
                if (n0v < NN)
                    *(__half2*)&xlh[n0v * OUTD + c] =
                        __floats2half2_rn(acc[mt][nt][0] + bv.x, acc[mt][nt][1] + bv.y);
                int n1v = n0v + 8;
                if (n1v < NN)
                    *(__half2*)&xlh[n1v * OUTD + c] =
                        __floats2half2_rn(acc[mt][nt][2] + bv.x, acc[mt][nt][3] + bv.y);
            }
        } else {
            int cc = c - OUTD;
            float2 bv = *(const float2*)&br[cc];
            #pragma unroll
            for (int mt = 0; mt < 2; mt++) {
                int n0v = node0 + rbase + mt * 16 + g;
                if (n0v < NN)
                    *(float2*)&xr[n0v * OUTD + cc] =
                        make_float2(acc[mt][nt][0] + bv.x, acc[mt][nt][1] + bv.y);
                int n1v = n0v + 8;
                if (n1v < NN)
                    *(float2*)&xr[n1v * OUTD + cc] =
                        make_float2(acc[mt][nt][2] + bv.x, acc[mt][nt][3] + bv.y);
            }
        }
    }
}

// ---------------- layer-1 fused: per-node logits MMA + softmax aggregate --------
// One warp per dst node. Edge tiles of 16 from its CSR range.
__global__ __launch_bounds__(256) void fused_attn1(
    const float* __restrict__ ea, const float* __restrict__ att,
    const float* __restrict__ bias) {
    int tid = threadIdx.x;
    int w = tid >> 5, lane = tid & 31, g = lane >> 2, t4 = lane & 3;
    int i = blockIdx.x * 8 + w;
    if (i >= NN) return;
    int start = g_rowptr[i], end = g_rowptr[i + 1];

    const float* xrr = g_xr1 + i * HCD;   // dst row, shared by all edges of this warp
    int c0 = 4 * lane;                    // channels owned for accumulation
    int hl = lane >> 3;                   // head of those channels

    float den = 0.f, a0 = 0.f, a1 = 0.f, a2 = 0.f, a3 = 0.f;

    for (int base = start; base < end; base += 16) {
        int s0i = base + g, s1i = base + 8 + g;
        bool v0 = s0i < end, v1 = s1i < end;
        int4 sd0 = g_sde[v0 ? s0i : start];
        int4 sd1 = g_sde[v1 ? s1i : start];
        int e0 = sd0.z, e1 = sd1.z;

        float d[16][4];
        #pragma unroll
        for (int nt = 0; nt < 16; nt++)
            #pragma unroll
            for (int q = 0; q < 4; q++) d[nt][q] = 0.f;

        #pragma unroll
        for (int kt = 0; kt < 4; kt++) {
            const float* p0 = ea + e0 * 32 + kt * 8 + t4;
            const float* p1 = ea + e1 * 32 + kt * 8 + t4;
            unsigned fa0 = tf32_of(__ldg(p0));
            unsigned fa1 = tf32_of(__ldg(p1));
            unsigned fa2 = tf32_of(__ldg(p0 + 4));
            unsigned fa3 = tf32_of(__ldg(p1 + 4));
            const uint2* wrow = g_We1p + (kt * 16) * 32 + lane;
            #pragma unroll
            for (int nt = 0; nt < 16; nt++) {
                uint2 b = __ldg(wrow + nt * 32);
                mma_tf32(d[nt], fa0, fa1, fa2, fa3, b.x, b.y);
            }
        }

        const __half2* xl0 = (const __half2*)(g_xl1h + sd0.x * HCD);
        const __half2* xl1 = (const __half2*)(g_xl1h + sd1.x * HCD);
        float p0h[4] = {0.f, 0.f, 0.f, 0.f};
        float p1h[4] = {0.f, 0.f, 0.f, 0.f};
        #pragma unroll
        for (int nt = 0; nt < 16; nt++) {
            int c = nt * 8 + t4 * 2;
            float2 atv = *(const float2*)&att[c];
            float2 xrv = *(const float2*)&xrr[c];
            float2 xa = __half22float2(xl0[nt * 4 + t4]);
            float v0f = d[nt][0] + xa.x + xrv.x;
            float v1f = d[nt][1] + xa.y + xrv.y;
            p0h[nt >> 2] += lrelu(v0f) * atv.x + lrelu(v1f) * atv.y;
            float2 xc = __half22float2(xl1[nt * 4 + t4]);
            float u0f = d[nt][2] + xc.x + xrv.x;
            float u1f = d[nt][3] + xc.y + xrv.y;
            p1h[nt >> 2] += lrelu(u0f) * atv.x + lrelu(u1f) * atv.y;
        }
        #pragma unroll
        for (int h = 0; h < 4; h++) {
            p0h[h] += __shfl_xor_sync(0xffffffffu, p0h[h], 1);
            p0h[h] += __shfl_xor_sync(0xffffffffu, p0h[h], 2);
            p1h[h] += __shfl_xor_sync(0xffffffffu, p1h[h], 1);
            p1h[h] += __shfl_xor_sync(0xffffffffu, p1h[h], 2);
        }
        float lg0 = (t4 == 0) ? p0h[0] : (t4 == 1) ? p0h[1] : (t4 == 2) ? p0h[2] : p0h[3];
        float lg1 = (t4 == 0) ? p1h[0] : (t4 == 1) ? p1h[1] : (t4 == 2) ? p1h[2] : p1h[3];
        float myw0 = v0 ? __expf(lg0) : 0.f;
        float myw1 = v1 ? __expf(lg1) : 0.f;

        // phase 2: accumulate over the tile's 16 edges (xl rows are L1-hot)
        int nvalid = end - base; if (nvalid > 16) nvalid = 16;
        int nfirst = nvalid < 8 ? nvalid : 8;
        for (int k = 0; k < nfirst; k++) {
            float wA = __shfl_sync(0xffffffffu, myw0, k * 4 + hl);
            int sA = __shfl_sync(0xffffffffu, sd0.x, k * 4);
            uint2 raw = *(const uint2*)&g_xl1h[sA * HCD + c0];
            float2 x0 = __half22float2(*(__half2*)&raw.x);
            float2 x1 = __half22float2(*(__half2*)&raw.y);
            den += wA;
            a0 = fmaf(wA, x0.x, a0);
            a1 = fmaf(wA, x0.y, a1);
            a2 = fmaf(wA, x1.x, a2);
            a3 = fmaf(wA, x1.y, a3);
        }
        int nsecond = nvalid - 8;
        for (int k = 0; k < nsecond; k++) {
            float wB = __shfl_sync(0xffffffffu, myw1, k * 4 + hl);
            int sB = __shfl_sync(0xffffffffu, sd1.x, k * 4);
            uint2 raw = *(const uint2*)&g_xl1h[sB * HCD + c0];
            float2 x0 = __half22float2(*(__half2*)&raw.x);
            float2 x1 = __half22float2(*(__half2*)&raw.y);
            den += wB;
            a0 = fmaf(wB, x0.x, a0);
            a1 = fmaf(wB, x0.y, a1);
            a2 = fmaf(wB, x1.x, a2);
            a3 = fmaf(wB, x1.y, a3);
        }
    }

    float inv = 1.f / (den + 1e-16f);
    float4 bv = *(const float4*)&bias[c0];
    float o0 = a0 * inv + bv.x;
    float o1 = a1 * inv + bv.y;
    float o2 = a2 * inv + bv.z;
    float o3 = a3 * inv + bv.w;
    o0 = o0 > 0.f ? o0 : expm1f(o0);
    o1 = o1 > 0.f ? o1 : expm1f(o1);
    o2 = o2 > 0.f ? o2 : expm1f(o2);
    o3 = o3 > 0.f ? o3 : expm1f(o3);
    *(float4*)&g_h[i * HCD + c0] = make_float4(o0, o1, o2, o3);
}

// ---------------- layer-2 fused: per-node logits MMA + softmax aggregate --------
__global__ __launch_bounds__(256) void fused_attn2(
    const float* __restrict__ ea, const float* __restrict__ att,
    const float* __restrict__ bias, float* __restrict__ out) {
    int tid = threadIdx.x;
    int w = tid >> 5, lane = tid & 31, g = lane >> 2, t4 = lane & 3;
    int i = blockIdx.x * 8 + w;
    if (i >= NN) return;
    int start = g_rowptr[i], end = g_rowptr[i + 1];

    const float* xrr = g_xr2 + i * OUTC;
    int c0 = 2 * lane;

    float den = 0.f, a0 = 0.f, a1 = 0.f;

    for (int base = start; base < end; base += 16) {
        int s0i = base + g, s1i = base + 8 + g;
        bool v0 = s0i < end, v1 = s1i < end;
        int4 sd0 = g_sde[v0 ? s0i : start];
        int4 sd1 = g_sde[v1 ? s1i : start];
        int e0 = sd0.z, e1 = sd1.z;

        float d[8][4];
        #pragma unroll
        for (int nt = 0; nt < 8; nt++)
            #pragma unroll
            for (int q = 0; q < 4; q++) d[nt][q] = 0.f;

        #pragma unroll
        for (int kt = 0; kt < 4; kt++) {
            const float* p0 = ea + e0 * 32 + kt * 8 + t4;
            const float* p1 = ea + e1 * 32 + kt * 8 + t4;
            unsigned fa0 = tf32_of(__ldg(p0));
            unsigned fa1 = tf32_of(__ldg(p1));
            unsigned fa2 = tf32_of(__ldg(p0 + 4));
            unsigned fa3 = tf32_of(__ldg(p1 + 4));
            const uint2* wrow = g_We2p + (kt * 8) * 32 + lane;
            #pragma unroll
            for (int nt = 0; nt < 8; nt++) {
                uint2 b = __ldg(wrow + nt * 32);
                mma_tf32(d[nt], fa0, fa1, fa2, fa3, b.x, b.y);
            }
        }

        const __half2* xl0 = (const __half2*)(g_xl2h + sd0.x * OUTC);
        const __half2* xl1 = (const __half2*)(g_xl2h + sd1.x * OUTC);
        float ps0 = 0.f, ps1 = 0.f;
        #pragma unroll
        for (int nt = 0; nt < 8; nt++) {
            int c = nt * 8 + t4 * 2;
            float2 atv = *(const float2*)&att[c];
            float2 xrv = *(const float2*)&xrr[c];
            float2 xa = __half22float2(xl0[nt * 4 + t4]);
            float v0f = d[nt][0] + xa.x + xrv.x;
            float v1f = d[nt][1] + xa.y + xrv.y;
            ps0 += lrelu(v0f) * atv.x + lrelu(v1f) * atv.y;
            float2 xc = __half22float2(xl1[nt * 4 + t4]);
            float u0f = d[nt][2] + xc.x + xrv.x;
            float u1f = d[nt][3] + xc.y + xrv.y;
            ps1 += lrelu(u0f) * atv.x + lrelu(u1f) * atv.y;
        }
        ps0 += __shfl_xor_sync(0xffffffffu, ps0, 1);
        ps0 += __shfl_xor_sync(0xffffffffu, ps0, 2);
        ps1 += __shfl_xor_sync(0xffffffffu, ps1, 1);
        ps1 += __shfl_xor_sync(0xffffffffu, ps1, 2);
        float myw0 = v0 ? __expf(ps0) : 0.f;
        float myw1 = v1 ? __expf(ps1) : 0.f;

        int nvalid = end - base; if (nvalid > 16) nvalid = 16;
        int nfirst = nvalid < 8 ? nvalid : 8;
        for (int k = 0; k < nfirst; k++) {
            float wA = __shfl_sync(0xffffffffu, myw0, k * 4);
            int sA = __shfl_sync(0xffffffffu, sd0.x, k * 4);
            float2 xv = __half22float2(*(const __half2*)&g_xl2h[sA * OUTC + c0]);
            den += wA;
            a0 = fmaf(wA, xv.x, a0);
            a1 = fmaf(wA, xv.y, a1);
        }
        int nsecond = nvalid - 8;
        for (int k = 0; k < nsecond; k++) {
            float wB = __shfl_sync(0xffffffffu, myw1, k * 4);
            int sB = __shfl_sync(0xffffffffu, sd1.x, k * 4);
            float2 xv = __half22float2(*(const __half2*)&g_xl2h[sB * OUTC + c0]);
            den += wB;
            a0 = fmaf(wB, xv.x, a0);
            a1 = fmaf(wB, xv.y, a1);
        }
    }

    float inv = 1.f / (den + 1e-16f);
    float o0 = a0 * inv + bias[c0];
    float o1 = a1 * inv + bias[c0 + 1];
    *(float2*)&out[i * OUTC + c0] = make_float2(o0, o1);
}

// ---------------- host launcher ---------------------------------------------------
extern "C" void kernel_launch(void* const* d_in, const int* in_sizes, int n_in,
                              void* d_out, int out_size) {
    const float* x    = (const float*)d_in[0];
    const int*   ei   = (const int*)  d_in[1];
    const float* ea   = (const float*)d_in[2];
    const float* Wl1  = (const float*)d_in[3];
    const float* bl1  = (const float*)d_in[4];
    const float* Wr1  = (const float*)d_in[5];
    const float* br1  = (const float*)d_in[6];
    const float* We1  = (const float*)d_in[7];
    const float* att1 = (const float*)d_in[8];
    const float* bias1= (const float*)d_in[9];
    const float* Wl2  = (const float*)d_in[10];
    const float* bl2  = (const float*)d_in[11];
    const float* Wr2  = (const float*)d_in[12];
    const float* br2  = (const float*)d_in[13];
    const float* We2  = (const float*)d_in[14];
    const float* att2 = (const float*)d_in[15];
    const float* bias2= (const float*)d_in[16];

    const int* src = ei;
    const int* dst = ei + EE;

    void *p_xl1h, *p_xr1, *p_h, *p_xl2h, *p_xr2, *p_deg, *p_W1p, *p_W2p;
    cudaGetSymbolAddress(&p_xl1h, g_xl1h);
    cudaGetSymbolAddress(&p_xr1, g_xr1);
    cudaGetSymbolAddress(&p_h,   g_h);
    cudaGetSymbolAddress(&p_xl2h, g_xl2h);
    cudaGetSymbolAddress(&p_xr2, g_xr2);
    cudaGetSymbolAddress(&p_deg, g_deg);
    cudaGetSymbolAddress(&p_W1p, g_W1p);
    cudaGetSymbolAddress(&p_W2p, g_W2p);

    // one-time host-side stream/event objects (no device memory involved)
    static cudaStream_t s_csr = nullptr;
    static cudaEvent_t ev_fork = nullptr, ev_csr_done = nullptr;
    if (s_csr == nullptr) {
        cudaStreamCreateWithFlags(&s_csr, cudaStreamNonBlocking);
        cudaEventCreateWithFlags(&ev_fork, cudaEventDisableTiming);
        cudaEventCreateWithFlags(&ev_csr_done, cudaEventDisableTiming);
    }

    // fork: CSR branch on s_csr, weight-prep + transform1 on main stream
    cudaEventRecord(ev_fork, 0);
    cudaStreamWaitEvent(s_csr, ev_fork, 0);

    // --- CSR branch (side stream) ---
    cudaMemsetAsync(p_deg, 0, NN * sizeof(int), s_csr);
    csr_count_kernel<<<(EE / 4 + 255) / 256, 256, 0, s_csr>>>(dst);
    scan_kernel<<<1, 1024, 0, s_csr>>>();
    csr_fill_kernel<<<(EE + 255) / 256, 256, 0, s_csr>>>(src, dst);
    cudaEventRecord(ev_csr_done, s_csr);

    // --- main branch ---
    prepack_kernel<<<108, 256>>>(Wl1, Wr1, Wl2, Wr2, We1, We2);
    transform_staged<HCD, 256><<<dim3((NN + 127) / 128, 2), 256>>>(
        x, (const uint2*)p_W1p, bl1, br1, (__half*)p_xl1h, (float*)p_xr1);

    // join: fused1 needs CSR + transform1 + prepack
    cudaStreamWaitEvent(0, ev_csr_done, 0);

    fused_attn1<<<(NN + 7) / 8, 256>>>(ea, att1, bias1);

    // layer 2
    transform_staged<OUTC, 128><<<dim3((NN + 127) / 128, 1), 256>>>(
        (const float*)p_h, (const uint2*)p_W2p, bl2, br2, (__half*)p_xl2h, (float*)p_xr2);
    fused_attn2<<<(NN + 7) / 8, 256>>>(ea, att2, bias2, (float*)d_out);
}

// round 15
// speedup vs baseline: 1.1281x; 1.1281x over previous
#include <cuda_runtime.h>
#include <cuda_fp16.h>
#include <math.h>

#define NN 50000
#define EE 800000
#define HCD 128
#define HEADS 4
#define OUTC 64
#define ED 32
#define NEG 0.2f

// ---------------- scratch (device globals) ------------------------------------
__device__ __half g_xl1h[NN * HCD];   // fp16 source-transform (gathered twice/edge)
__device__ float  g_xr1[NN * HCD];
__device__ float  g_h  [NN * HCD];
__device__ __half g_xl2h[NN * OUTC];
__device__ float  g_xr2[NN * OUTC];
__device__ float  g_a1p[EE * HEADS];  // exp(logit), CSR slot order, [slot][head]
__device__ float  g_a2p[EE];          // exp(logit), CSR slot order
__device__ int    g_deg[NN];
__device__ int    g_rowptr[NN + 1];
__device__ int    g_cursor[NN];
__device__ int4   g_sde[EE];          // CSR slot -> {src, dst, edge, 0}
// pre-packed tf32 B-fragments: [kt][ntg][lane]{b0,b1}
__device__ uint2 g_W1p[16 * 32 * 32];
__device__ uint2 g_W2p[16 * 16 * 32];
__device__ uint2 g_We1p[4 * 16 * 32];
__device__ uint2 g_We2p[4 * 8 * 32];

// ---------------- helpers -------------------------------------------------------
__device__ __forceinline__ unsigned tf32_of(float f) {
    unsigned r;
    asm("cvt.rna.tf32.f32 %0, %1;" : "=r"(r) : "f"(f));
    return r;
}
__device__ __forceinline__ void mma_tf32(float* d,
                                         unsigned a0, unsigned a1, unsigned a2, unsigned a3,
                                         unsigned b0, unsigned b1) {
    asm volatile(
        "mma.sync.aligned.m16n8k8.row.col.f32.tf32.tf32.f32 "
        "{%0,%1,%2,%3}, {%4,%5,%6,%7}, {%8,%9}, {%0,%1,%2,%3};"
        : "+f"(d[0]), "+f"(d[1]), "+f"(d[2]), "+f"(d[3])
        : "r"(a0), "r"(a1), "r"(a2), "r"(a3), "r"(b0), "r"(b1));
}
__device__ __forceinline__ float lrelu(float x) { return x > 0.f ? x : NEG * x; }

// ---------------- weight fragment pre-pack --------------------------------------
__global__ void prepack_kernel(const float* __restrict__ Wl1, const float* __restrict__ Wr1,
                               const float* __restrict__ Wl2, const float* __restrict__ Wr2,
                               const float* __restrict__ We1, const float* __restrict__ We2) {
    int gw = blockIdx.x * 8 + (threadIdx.x >> 5);
    int lane = threadIdx.x & 31, g = lane >> 2, t4 = lane & 3;
    if (gw < 512) {
        int kt = gw >> 5, ntg = gw & 31;
        int c = ntg * 8 + g, k0 = kt * 8 + t4;
        float v0 = (c < 128) ? Wl1[k0 * 128 + c] : Wr1[k0 * 128 + c - 128];
        float v1 = (c < 128) ? Wl1[(k0 + 4) * 128 + c] : Wr1[(k0 + 4) * 128 + c - 128];
        g_W1p[(kt * 32 + ntg) * 32 + lane] = make_uint2(tf32_of(v0), tf32_of(v1));
    } else if (gw < 768) {
        int r = gw - 512;
        int kt = r >> 4, ntg = r & 15;
        int c = ntg * 8 + g, k0 = kt * 8 + t4;
        float v0 = (c < 64) ? Wl2[k0 * 64 + c] : Wr2[k0 * 64 + c - 64];
        float v1 = (c < 64) ? Wl2[(k0 + 4) * 64 + c] : Wr2[(k0 + 4) * 64 + c - 64];
        g_W2p[(kt * 16 + ntg) * 32 + lane] = make_uint2(tf32_of(v0), tf32_of(v1));
    } else if (gw < 832) {
        int r = gw - 768;
        int kt = r >> 4, ntg = r & 15;
        int c = ntg * 8 + g, k0 = kt * 8 + t4;
        g_We1p[(kt * 16 + ntg) * 32 + lane] =
            make_uint2(tf32_of(We1[k0 * 128 + c]), tf32_of(We1[(k0 + 4) * 128 + c]));
    } else if (gw < 864) {
        int r = gw - 832;
        int kt = r >> 3, ntg = r & 7;
        int c = ntg * 8 + g, k0 = kt * 8 + t4;
        g_We2p[(kt * 8 + ntg) * 32 + lane] =
            make_uint2(tf32_of(We2[k0 * 64 + c]), tf32_of(We2[(k0 + 4) * 64 + c]));
    }
}

// ---------------- CSR build -----------------------------------------------------
__global__ void csr_count_kernel(const int* __restrict__ dst) {
    int t = blockIdx.x * blockDim.x + threadIdx.x;
    int e4 = t * 4;
    if (e4 < EE) {
        int4 d = *(const int4*)&dst[e4];
        atomicAdd(&g_deg[d.x], 1);
        atomicAdd(&g_deg[d.y], 1);
        atomicAdd(&g_deg[d.z], 1);
        atomicAdd(&g_deg[d.w], 1);
    }
}

__global__ void scan_kernel() {
    __shared__ int wtot[32];
    __shared__ int carry_sm;
    int t = threadIdx.x, lane = t & 31, wid = t >> 5;
    if (t == 0) carry_sm = 0;
    __syncthreads();
    for (int base = 0; base < NN; base += 4096) {
        int carry = carry_sm;
        int idx = base + t * 4;
        int4 v = make_int4(0, 0, 0, 0);
        if (idx + 3 < NN) v = *(const int4*)&g_deg[idx];
        else {
            if (idx     < NN) v.x = g_deg[idx];
            if (idx + 1 < NN) v.y = g_deg[idx + 1];
            if (idx + 2 < NN) v.z = g_deg[idx + 2];
        }
        int s1 = v.x + v.y, s2 = s1 + v.z, tsum = s2 + v.w;
        int sc = tsum;
        #pragma unroll
        for (int off = 1; off < 32; off <<= 1) {
            int u = __shfl_up_sync(0xffffffffu, sc, off);
            if (lane >= off) sc += u;
        }
        if (lane == 31) wtot[wid] = sc;
        __syncthreads();
        if (wid == 0) {
            int wv = wtot[lane];
            int ws = wv;
            #pragma unroll
            for (int off = 1; off < 32; off <<= 1) {
                int u = __shfl_up_sync(0xffffffffu, ws, off);
                if (lane >= off) ws += u;
            }
            wtot[lane] = ws - wv;
        }
        __syncthreads();
        int off0 = carry + wtot[wid] + (sc - tsum);
        if (idx     < NN) { g_rowptr[idx]     = off0;        g_cursor[idx]     = off0; }
        if (idx + 1 < NN) { int o = off0 + v.x; g_rowptr[idx + 1] = o; g_cursor[idx + 1] = o; }
        if (idx + 2 < NN) { int o = off0 + s1;  g_rowptr[idx + 2] = o; g_cursor[idx + 2] = o; }
        if (idx + 3 < NN) { int o = off0 + s2;  g_rowptr[idx + 3] = o; g_cursor[idx + 3] = o; }
        if (t == 1023) carry_sm = carry + wtot[31] + sc;
        __syncthreads();
    }
    if (t == 0) g_rowptr[NN] = EE;
}

__global__ void csr_fill_kernel(const int* __restrict__ src, const int* __restrict__ dst) {
    int e = blockIdx.x * blockDim.x + threadIdx.x;
    if (e < EE) {
        int d = dst[e];
        int pos = atomicAdd(&g_cursor[d], 1);
        g_sde[pos] = make_int4(src[e], d, e, 0);
    }
}

// ---------------- node transform: smem-staged A + direct-LDG B tf32 MMA ---------
template<int OUTD, int TC>
__global__ __launch_bounds__(256) void transform_staged(
    const float* __restrict__ x, const uint2* __restrict__ Wp,
    const float* __restrict__ bl, const float* __restrict__ br,
    __half* __restrict__ xlh, float* __restrict__ xr) {
    constexpr int NTT = TC / 8;
    __shared__ unsigned xs[128 * 68];
    int tid = threadIdx.x;
    int w = tid >> 5, lane = tid & 31, g = lane >> 2, t4 = lane & 3;
    int mrow = w & 3, ncol = w >> 2;
    int node0 = blockIdx.x * 128;
    int rbase = mrow * 32;
    int ntbase = blockIdx.y * 16 + ncol * 8;

    float acc[2][8][4];
    #pragma unroll
    for (int mt = 0; mt < 2; mt++)
        #pragma unroll
        for (int nt = 0; nt < 8; nt++)
            #pragma unroll
            for (int i = 0; i < 4; i++) acc[mt][nt][i] = 0.f;

    #pragma unroll
    for (int ch = 0; ch < 2; ch++) {
        __syncthreads();
        for (int idx = tid; idx < 128 * 16; idx += 256) {
            int r = idx >> 4, q = idx & 15;
            int row = node0 + r;
            float4 v = make_float4(0.f, 0.f, 0.f, 0.f);
            if (row < NN) v = *(const float4*)&x[row * 128 + ch * 64 + q * 4];
            uint4 u;
            u.x = tf32_of(v.x); u.y = tf32_of(v.y);
            u.z = tf32_of(v.z); u.w = tf32_of(v.w);
            *(uint4*)&xs[r * 68 + q * 4] = u;
        }
        __syncthreads();
        #pragma unroll
        for (int ktl = 0; ktl < 8; ktl++) {
            int kt = ch * 8 + ktl;
            unsigned a[2][4];
            #pragma unroll
            for (int mt = 0; mt < 2; mt++) {
                int r0 = (rbase + mt * 16 + g) * 68 + ktl * 8 + t4;
                a[mt][0] = xs[r0];
                a[mt][1] = xs[r0 + 8 * 68];
                a[mt][2] = xs[r0 + 4];
                a[mt][3] = xs[r0 + 8 * 68 + 4];
            }
            const uint2* wrow = Wp + (kt * NTT + ntbase) * 32 + lane;
            #pragma unroll
            for (int nt = 0; nt < 8; nt++) {
                uint2 b = __ldg(wrow + nt * 32);
                mma_tf32(acc[0][nt], a[0][0], a[0][1], a[0][2], a[0][3], b.x, b.y);
                mma_tf32(acc[1][nt], a[1][0], a[1][1], a[1][2], a[1][3], b.x, b.y);
            }
        }
    }

    #pragma unroll
    for (int nt = 0; nt < 8; nt++) {
        int c = (ntbase + nt) * 8 + t4 * 2;
        if (c < OUTD) {
            float2 bv = *(const float2*)&bl[c];
            #pragma unroll
            for (int mt = 0; mt < 2; mt++) {
                int n0v = node0 + rbase + mt * 16 + g;
                if (n0v < NN)
                    *(__half2*)&xlh[n0v * OUTD + c] =
                        __floats2half2_rn(acc[mt][nt][0] + bv.x, acc[mt][nt][1] + bv.y);
                int n1v = n0v + 8;
                if (n1v < NN)
                    *(__half2*)&xlh[n1v * OUTD + c] =
                        __floats2half2_rn(acc[mt][nt][2] + bv.x, acc[mt][nt][3] + bv.y);
            }
        } else {
            int cc = c - OUTD;
            float2 bv = *(const float2*)&br[cc];
            #pragma unroll
            for (int mt = 0; mt < 2; mt++) {
                int n0v = node0 + rbase + mt * 16 + g;
                if (n0v < NN)
                    *(float2*)&xr[n0v * OUTD + cc] =
                        make_float2(acc[mt][nt][0] + bv.x, acc[mt][nt][1] + bv.y);
                int n1v = n0v + 8;
                if (n1v < NN)
                    *(float2*)&xr[n1v * OUTD + cc] =
                        make_float2(acc[mt][nt][2] + bv.x, acc[mt][nt][3] + bv.y);
            }
        }
    }
}

// ---------------- layer-1 edge logits: CSR-ordered tf32 MMA ---------------------
__global__ __launch_bounds__(256) void edge_logits1_direct(
    const float* __restrict__ ea, const float* __restrict__ att) {
    int tid = threadIdx.x;
    int w = tid >> 5, lane = tid & 31, g = lane >> 2, t4 = lane & 3;
    int sbase = blockIdx.x * 128 + w * 16;

    int4 sd0 = g_sde[sbase + g];
    int4 sd1 = g_sde[sbase + 8 + g];
    int e0 = sd0.z, e1 = sd1.z;

    // preload loop-invariant att values into registers
    float2 areg[16];
    #pragma unroll
    for (int nt = 0; nt < 16; nt++)
        areg[nt] = *(const float2*)&att[nt * 8 + t4 * 2];

    float d[16][4];
    #pragma unroll
    for (int nt = 0; nt < 16; nt++)
        #pragma unroll
        for (int i = 0; i < 4; i++) d[nt][i] = 0.f;

    #pragma unroll
    for (int kt = 0; kt < 4; kt++) {
        const float* p0 = ea + e0 * 32 + kt * 8 + t4;
        const float* p1 = ea + e1 * 32 + kt * 8 + t4;
        unsigned a0 = tf32_of(__ldg(p0));
        unsigned a1 = tf32_of(__ldg(p1));
        unsigned a2 = tf32_of(__ldg(p0 + 4));
        unsigned a3 = tf32_of(__ldg(p1 + 4));
        const uint2* wrow = g_We1p + (kt * 16) * 32 + lane;
        #pragma unroll
        for (int nt = 0; nt < 16; nt++) {
            uint2 b = __ldg(wrow + nt * 32);
            mma_tf32(d[nt], a0, a1, a2, a3, b.x, b.y);
        }
    }

    const __half2* xl0 = (const __half2*)(g_xl1h + sd0.x * HCD);
    const float*   xr0 = g_xr1 + sd0.y * HCD;
    const __half2* xl1r = (const __half2*)(g_xl1h + sd1.x * HCD);
    const float*   xr1r = g_xr1 + sd1.y * HCD;
    float p0h[4] = {0.f, 0.f, 0.f, 0.f};
    float p1h[4] = {0.f, 0.f, 0.f, 0.f};
    #pragma unroll
    for (int nt = 0; nt < 16; nt++) {
        int c = nt * 8 + t4 * 2;
        float2 atv = areg[nt];
        float2 xa = __half22float2(xl0[nt * 4 + t4]);
        float2 xb = *(const float2*)&xr0[c];
        float v0 = d[nt][0] + xa.x + xb.x;
        float v1 = d[nt][1] + xa.y + xb.y;
        p0h[nt >> 2] += lrelu(v0) * atv.x + lrelu(v1) * atv.y;
        float2 xc = __half22float2(xl1r[nt * 4 + t4]);
        float2 xd = *(const float2*)&xr1r[c];
        float u0 = d[nt][2] + xc.x + xd.x;
        float u1 = d[nt][3] + xc.y + xd.y;
        p1h[nt >> 2] += lrelu(u0) * atv.x + lrelu(u1) * atv.y;
    }
    #pragma unroll
    for (int h = 0; h < 4; h++) {
        p0h[h] += __shfl_xor_sync(0xffffffffu, p0h[h], 1);
        p0h[h] += __shfl_xor_sync(0xffffffffu, p0h[h], 2);
        p1h[h] += __shfl_xor_sync(0xffffffffu, p1h[h], 1);
        p1h[h] += __shfl_xor_sync(0xffffffffu, p1h[h], 2);
    }
    float v0 = (t4 == 0) ? p0h[0] : (t4 == 1) ? p0h[1] : (t4 == 2) ? p0h[2] : p0h[3];
    float v1 = (t4 == 0) ? p1h[0] : (t4 == 1) ? p1h[1] : (t4 == 2) ? p1h[2] : p1h[3];
    g_a1p[(sbase + g) * HEADS + t4]     = __expf(v0);
    g_a1p[(sbase + 8 + g) * HEADS + t4] = __expf(v1);
}

// ---------------- layer-2 edge logits: CSR-ordered tf32 MMA ---------------------
__global__ __launch_bounds__(256) void edge_logits2_direct(
    const float* __restrict__ ea, const float* __restrict__ att) {
    int tid = threadIdx.x;
    int w = tid >> 5, lane = tid & 31, g = lane >> 2, t4 = lane & 3;
    int sbase = blockIdx.x * 128 + w * 16;

    int4 sd0 = g_sde[sbase + g];
    int4 sd1 = g_sde[sbase + 8 + g];
    int e0 = sd0.z, e1 = sd1.z;

    float2 areg[8];
    #pragma unroll
    for (int nt = 0; nt < 8; nt++)
        areg[nt] = *(const float2*)&att[nt * 8 + t4 * 2];

    float d[8][4];
    #pragma unroll
    for (int nt = 0; nt < 8; nt++)
        #pragma unroll
        for (int i = 0; i < 4; i++) d[nt][i] = 0.f;

    #pragma unroll
    for (int kt = 0; kt < 4; kt++) {
        const float* p0 = ea + e0 * 32 + kt * 8 + t4;
        const float* p1 = ea + e1 * 32 + kt * 8 + t4;
        unsigned a0 = tf32_of(__ldg(p0));
        unsigned a1 = tf32_of(__ldg(p1));
        unsigned a2 = tf32_of(__ldg(p0 + 4));
        unsigned a3 = tf32_of(__ldg(p1 + 4));
        const uint2* wrow = g_We2p + (kt * 8) * 32 + lane;
        #pragma unroll
        for (int nt = 0; nt < 8; nt++) {
            uint2 b = __ldg(wrow + nt * 32);
            mma_tf32(d[nt], a0, a1, a2, a3, b.x, b.y);
        }
    }

    const __half2* xl0 = (const __half2*)(g_xl2h + sd0.x * OUTC);
    const float*   xr0 = g_xr2 + sd0.y * OUTC;
    const __half2* xl1r = (const __half2*)(g_xl2h + sd1.x * OUTC);
    const float*   xr1r = g_xr2 + sd1.y * OUTC;
    float ps0 = 0.f, ps1 = 0.f;
    #pragma unroll
    for (int nt = 0; nt < 8; nt++) {
        int c = nt * 8 + t4 * 2;
        float2 atv = areg[nt];
        float2 xa = __half22float2(xl0[nt * 4 + t4]);
        float2 xb = *(const float2*)&xr0[c];
        float v0 = d[nt][0] + xa.x + xb.x;
        float v1 = d[nt][1] + xa.y + xb.y;
        ps0 += lrelu(v0) * atv.x + lrelu(v1) * atv.y;
        float2 xc = __half22float2(xl1r[nt * 4 + t4]);
        float2 xd = *(const float2*)&xr1r[c];
        float u0 = d[nt][2] + xc.x + xd.x;
        float u1 = d[nt][3] + xc.y + xd.y;
        ps1 += lrelu(u0) * atv.x + lrelu(u1) * atv.y;
    }
    ps0 += __shfl_xor_sync(0xffffffffu, ps0, 1);
    ps0 += __shfl_xor_sync(0xffffffffu, ps0, 2);
    ps1 += __shfl_xor_sync(0xffffffffu, ps1, 1);
    ps1 += __shfl_xor_sync(0xffffffffu, ps1, 2);
    if (t4 == 0) {
        g_a2p[sbase + g]     = __expf(ps0);
        g_a2p[sbase + 8 + g] = __expf(ps1);
    }
}

// ---------------- layer-1 aggregate: 2 warps/node, shuffle-broadcast ------------
__global__ void aggregate1_kernel(const float* __restrict__ bias) {
    int wi = (blockIdx.x * blockDim.x + threadIdx.x) >> 5;
    int lane = threadIdx.x & 31;
    int i = wi >> 1, half = wi & 1;
    if (i >= NN) return;
    int start = g_rowptr[i], end = g_rowptr[i + 1];
    int c0 = half * 64 + 2 * lane;
    int hsel = lane >> 4;

    float den = 0.f, a0 = 0.f, a1 = 0.f;
    for (int base = start; base < end; base += 32) {
        int n = end - base; if (n > 32) n = 32;
        float2 wv = make_float2(0.f, 0.f);
        int sv = 0;
        if (lane < n) {
            int slot = base + lane;
            wv = *(const float2*)&g_a1p[slot * HEADS + half * 2];
            sv = g_sde[slot].x;
        }
        for (int k = 0; k < n; k++) {
            float wx = __shfl_sync(0xffffffffu, wv.x, k);
            float wy = __shfl_sync(0xffffffffu, wv.y, k);
            int s = __shfl_sync(0xffffffffu, sv, k);
            float wgt = hsel ? wy : wx;
            float2 xv = __half22float2(*(const __half2*)&g_xl1h[s * HCD + c0]);
            den += wgt;
            a0 = fmaf(wgt, xv.x, a0);
            a1 = fmaf(wgt, xv.y, a1);
        }
    }
    float inv = 1.f / (den + 1e-16f);
    float2 bv = *(const float2*)&bias[c0];
    float o0 = a0 * inv + bv.x;
    float o1 = a1 * inv + bv.y;
    o0 = o0 > 0.f ? o0 : expm1f(o0);
    o1 = o1 > 0.f ? o1 : expm1f(o1);
    *(float2*)&g_h[i * HCD + c0] = make_float2(o0, o1);
}

// ---------------- layer-2 aggregate: 1 warp/node, shuffle-broadcast -------------
__global__ void aggregate2_kernel(const float* __restrict__ bias, float* __restrict__ out) {
    int i = (blockIdx.x * blockDim.x + threadIdx.x) >> 5;
    int lane = threadIdx.x & 31;
    if (i >= NN) return;
    int start = g_rowptr[i], end = g_rowptr[i + 1];
    int c0 = 2 * lane;

    float den = 0.f, a0 = 0.f, a1 = 0.f;
    for (int base = start; base < end; base += 32) {
        int n = end - base; if (n > 32) n = 32;
        float wv = 0.f;
        int sv = 0;
        if (lane < n) {
            int slot = base + lane;
            wv = g_a2p[slot];
            sv = g_sde[slot].x;
        }
        for (int k = 0; k < n; k++) {
            float wgt = __shfl_sync(0xffffffffu, wv, k);
            int s = __shfl_sync(0xffffffffu, sv, k);
            float2 xv = __half22float2(*(const __half2*)&g_xl2h[s * OUTC + c0]);
            den += wgt;
            a0 = fmaf(wgt, xv.x, a0);
            a1 = fmaf(wgt, xv.y, a1);
        }
    }
    float inv = 1.f / (den + 1e-16f);
    float o0 = a0 * inv + bias[c0];
    float o1 = a1 * inv + bias[c0 + 1];
    *(float2*)&out[i * OUTC + c0] = make_float2(o0, o1);
}

// ---------------- host launcher ---------------------------------------------------
extern "C" void kernel_launch(void* const* d_in, const int* in_sizes, int n_in,
                              void* d_out, int out_size) {
    const float* x    = (const float*)d_in[0];
    const int*   ei   = (const int*)  d_in[1];
    const float* ea   = (const float*)d_in[2];
    const float* Wl1  = (const float*)d_in[3];
    const float* bl1  = (const float*)d_in[4];
    const float* Wr1  = (const float*)d_in[5];
    const float* br1  = (const float*)d_in[6];
    const float* We1  = (const float*)d_in[7];
    const float* att1 = (const float*)d_in[8];
    const float* bias1= (const float*)d_in[9];
    const float* Wl2  = (const float*)d_in[10];
    const float* bl2  = (const float*)d_in[11];
    const float* Wr2  = (const float*)d_in[12];
    const float* br2  = (const float*)d_in[13];
    const float* We2  = (const float*)d_in[14];
    const float* att2 = (const float*)d_in[15];
    const float* bias2= (const float*)d_in[16];

    const int* src = ei;
    const int* dst = ei + EE;

    void *p_xl1h, *p_xr1, *p_h, *p_xl2h, *p_xr2, *p_deg, *p_W1p, *p_W2p;
    cudaGetSymbolAddress(&p_xl1h, g_xl1h);
    cudaGetSymbolAddress(&p_xr1, g_xr1);
    cudaGetSymbolAddress(&p_h,   g_h);
    cudaGetSymbolAddress(&p_xl2h, g_xl2h);
    cudaGetSymbolAddress(&p_xr2, g_xr2);
    cudaGetSymbolAddress(&p_deg, g_deg);
    cudaGetSymbolAddress(&p_W1p, g_W1p);
    cudaGetSymbolAddress(&p_W2p, g_W2p);

    // one-time host-side stream/event objects (no device memory involved)
    static cudaStream_t s_csr = nullptr;
    static cudaEvent_t ev_fork = nullptr, ev_csr_done = nullptr;
    if (s_csr == nullptr) {
        cudaStreamCreateWithFlags(&s_csr, cudaStreamNonBlocking);
        cudaEventCreateWithFlags(&ev_fork, cudaEventDisableTiming);
        cudaEventCreateWithFlags(&ev_csr_done, cudaEventDisableTiming);
    }

    // fork: CSR branch on s_csr, weight-prep + transform1 on main stream
    cudaEventRecord(ev_fork, 0);
    cudaStreamWaitEvent(s_csr, ev_fork, 0);

    // --- CSR branch (side stream) ---
    cudaMemsetAsync(p_deg, 0, NN * sizeof(int), s_csr);
    csr_count_kernel<<<(EE / 4 + 255) / 256, 256, 0, s_csr>>>(dst);
    scan_kernel<<<1, 1024, 0, s_csr>>>();
    csr_fill_kernel<<<(EE + 255) / 256, 256, 0, s_csr>>>(src, dst);
    cudaEventRecord(ev_csr_done, s_csr);

    // --- main branch ---
    prepack_kernel<<<108, 256>>>(Wl1, Wr1, Wl2, Wr2, We1, We2);
    transform_staged<HCD, 256><<<dim3((NN + 127) / 128, 2), 256>>>(
        x, (const uint2*)p_W1p, bl1, br1, (__half*)p_xl1h, (float*)p_xr1);

    // join: logits1 needs CSR + transform1 + prepack
    cudaStreamWaitEvent(0, ev_csr_done, 0);

    edge_logits1_direct<<<EE / 128, 256>>>(ea, att1);
    aggregate1_kernel<<<(2 * NN + 7) / 8, 256>>>(bias1);

    // layer 2
    transform_staged<OUTC, 128><<<dim3((NN + 127) / 128, 1), 256>>>(
        (const float*)p_h, (const uint2*)p_W2p, bl2, br2, (__half*)p_xl2h, (float*)p_xr2);
    edge_logits2_direct<<<EE / 128, 256>>>(ea, att2);
    aggregate2_kernel<<<NN / 8, 256>>>(bias2, (float*)d_out);
}